// round 16
// baseline (speedup 1.0000x reference)
#include <cuda_runtime.h>
#include <math.h>

#define D 4096
#define NK 24                 // 16 res + 4 pre + 4 post
#define TAU_INV 10.0f
#define RMS_EPS 1.1920929e-07f
#define NTOK 16384
#define CHUNKF 128            // fp32 elements of K per pipeline chunk
#define NCHUNK (D / CHUNKF)   // 32
#define STG_F4 1280           // float4 per stage: x 512 (16 tok) + W 768 (24 rows)

// Scratch (no cudaMalloc allowed)
__device__ float g_M[NTOK * 16];              // [token][16] mixing matrices
__device__ float g_W[NK * D];                 // packed W: 24 contiguous rows

typedef unsigned long long u64;

__device__ __forceinline__ u64 fma2(u64 a, u64 b, u64 c) {
    u64 d;
    asm("fma.rn.f32x2 %0, %1, %2, %3;" : "=l"(d) : "l"(a), "l"(b), "l"(c));
    return d;
}
__device__ __forceinline__ float pairsum(u64 v) {
    unsigned int lo, hi;
    asm("mov.b64 {%0, %1}, %2;" : "=r"(lo), "=r"(hi) : "l"(v));
    return __uint_as_float(lo) + __uint_as_float(hi);
}
__device__ __forceinline__ float warpSum(float v) {
    v += __shfl_xor_sync(0xffffffffu, v, 16);
    v += __shfl_xor_sync(0xffffffffu, v, 8);
    v += __shfl_xor_sync(0xffffffffu, v, 4);
    v += __shfl_xor_sync(0xffffffffu, v, 2);
    v += __shfl_xor_sync(0xffffffffu, v, 1);
    return v;
}
__device__ __forceinline__ float frcp(float x) {
    float y;
    asm("rcp.approx.f32 %0, %1;" : "=f"(y) : "f"(x));
    return y;
}

// ---------------------------------------------------------------------------
// pack W into one contiguous [24][4096] buffer
// ---------------------------------------------------------------------------
__global__ __launch_bounds__(256) void packW_kernel(
    const float* __restrict__ Wres,
    const float* __restrict__ Wpre,
    const float* __restrict__ Wpost)
{
    int i = blockIdx.x * 256 + threadIdx.x;       // float4 index, 24576 total
    int k = i >> 10;                              // row (1024 float4 per row)
    float4 v;
    if (k < 16)      v = reinterpret_cast<const float4*>(Wres)[i];
    else if (k < 20) v = reinterpret_cast<const float4*>(Wpre)[i - 16 * 1024];
    else             v = reinterpret_cast<const float4*>(Wpost)[i - 20 * 1024];
    reinterpret_cast<float4*>(g_W)[i] = v;
}

// ---------------------------------------------------------------------------
// FUSED logits + Sinkhorn kernel: one CTA = 16 tokens.
// Mainloop: EXACT R13/R15 logits configuration (1024 CTAs x 128 thr, 2 CTAs/SM,
//   warp = 6 rows x 16 tokens, 4-stage cp.async pipeline, 1 barrier/chunk).
// Epilogue A: warp reductions -> sLog[16][26] in stage-0 SMEM (safe: stage 0
//   last read at chunk 28; all warps are past the chunk-31 barrier).
// Epilogue B: threads 0..15 run probability-domain Sinkhorn(50) + softmaxes
//   + gate for one token each, write g_M directly. Tail (~3k cyc) overlaps
//   with other resident CTAs' mainloops except on the final wave.
// ---------------------------------------------------------------------------
__global__ __launch_bounds__(128, 2) void logits_kernel(
    const float* __restrict__ x,
    const float* __restrict__ HresB,
    const float* __restrict__ HpreB,
    const float* __restrict__ HpostB,
    const float* __restrict__ gate)
{
    extern __shared__ float4 smem[];              // 4 x 1280 float4 = 80KB

    const int tid  = threadIdx.x;
    const int lane = tid & 31;
    const int r    = tid >> 5;                    // warp = row group (6 rows)
    const int t0   = blockIdx.x * 16;

    unsigned int smem_base;
    asm("{ .reg .u64 t; cvta.to.shared.u64 t, %1; cvt.u32.u64 %0, t; }"
        : "=r"(smem_base) : "l"(smem));

    const float4* __restrict__ xsrc = reinterpret_cast<const float4*>(x);
    const float4* __restrict__ wsrc = reinterpret_cast<const float4*>(g_W);
    const ulonglong2* __restrict__ S = reinterpret_cast<const ulonglong2*>(smem);

    u64 acc[6][16];
#pragma unroll
    for (int i = 0; i < 6; ++i)
#pragma unroll
        for (int t = 0; t < 16; ++t) acc[i][t] = 0ULL;
    u64 ss[4] = {0ULL, 0ULL, 0ULL, 0ULL};        // sumsq: tokens with (t&3)==r

    // ---- stage issuer: 10 cp.asyncs/thread (x: 512 f4, W: 768 f4) ----
    auto issue_stage = [&](int stg, int c) {
#pragma unroll
        for (int n = 0; n < 10; ++n) {
            int i = n * 128 + tid;                // 0..1279
            const float4* src;
            if (n < 4) {                          // i < 512 : x (16 tokens x 32 f4)
                int t = i >> 5;
                int f = i & 31;
                src = xsrc + (size_t)(t0 + t) * 1024 + c * 32 + f;
            } else {                              // W (24 rows x 32 f4)
                int k = (i - 512) >> 5;
                int f = i & 31;
                src = wsrc + k * 1024 + c * 32 + f;
            }
            unsigned int dst = smem_base + (unsigned)(stg * STG_F4 + i) * 16u;
            asm volatile("cp.async.cg.shared.global [%0], [%1], 16;"
                         :: "r"(dst), "l"(src) : "memory");
        }
        asm volatile("cp.async.commit_group;" ::: "memory");
    };

    issue_stage(0, 0);
    issue_stage(1, 1);
    issue_stage(2, 2);

#pragma unroll 1
    for (int c = 0; c < NCHUNK; ++c) {
        if (c <= NCHUNK - 3)      asm volatile("cp.async.wait_group 2;" ::: "memory");
        else if (c == NCHUNK - 2) asm volatile("cp.async.wait_group 1;" ::: "memory");
        else                      asm volatile("cp.async.wait_group 0;" ::: "memory");
        __syncthreads();                          // single barrier per chunk

        if (c + 3 < NCHUNK) issue_stage((c + 3) & 3, c + 3);

        const int sb = (c & 3) * STG_F4;          // 16B units

        // 6 W rows for this warp, held in registers across the token loop
        ulonglong2 w0 = S[sb + 512 + (6 * r + 0) * 32 + lane];
        ulonglong2 w1 = S[sb + 512 + (6 * r + 1) * 32 + lane];
        ulonglong2 w2 = S[sb + 512 + (6 * r + 2) * 32 + lane];
        ulonglong2 w3 = S[sb + 512 + (6 * r + 3) * 32 + lane];
        ulonglong2 w4 = S[sb + 512 + (6 * r + 4) * 32 + lane];
        ulonglong2 w5 = S[sb + 512 + (6 * r + 5) * 32 + lane];

#pragma unroll
        for (int t = 0; t < 16; ++t) {
            ulonglong2 a = S[sb + t * 32 + lane];
            acc[0][t] = fma2(a.x, w0.x, acc[0][t]);
            acc[0][t] = fma2(a.y, w0.y, acc[0][t]);
            acc[1][t] = fma2(a.x, w1.x, acc[1][t]);
            acc[1][t] = fma2(a.y, w1.y, acc[1][t]);
            acc[2][t] = fma2(a.x, w2.x, acc[2][t]);
            acc[2][t] = fma2(a.y, w2.y, acc[2][t]);
            acc[3][t] = fma2(a.x, w3.x, acc[3][t]);
            acc[3][t] = fma2(a.y, w3.y, acc[3][t]);
            acc[4][t] = fma2(a.x, w4.x, acc[4][t]);
            acc[4][t] = fma2(a.y, w4.y, acc[4][t]);
            acc[5][t] = fma2(a.x, w5.x, acc[5][t]);
            acc[5][t] = fma2(a.y, w5.y, acc[5][t]);
            if ((t & 3) == r) {
                ss[t >> 2] = fma2(a.x, a.x, ss[t >> 2]);
                ss[t >> 2] = fma2(a.y, a.y, ss[t >> 2]);
            }
        }
    }

    // ---- epilogue A: reduce into SMEM sLog[16][26] (stage-0 bytes, safe) ----
    float* sLog = reinterpret_cast<float*>(smem);
#pragma unroll
    for (int i = 0; i < 6; ++i) {
#pragma unroll
        for (int t = 0; t < 16; ++t) {
            float v = warpSum(pairsum(acc[i][t]));
            if (lane == 0) sLog[t * 26 + 6 * r + i] = v;
        }
    }
#pragma unroll
    for (int m = 0; m < 4; ++m) {
        float v = warpSum(pairsum(ss[m]));
        if (lane == 0) sLog[(4 * m + r) * 26 + 24] = v;
    }
    __syncthreads();

    // ---- epilogue B: Sinkhorn (prob domain) + softmaxes + gate -> g_M ----
    if (tid < 16) {
        const float* Lg = sLog + tid * 26;
        float rms = rsqrtf(Lg[24] * (1.0f / (float)D) + RMS_EPS);

        float Z[16];
#pragma unroll
        for (int ij = 0; ij < 16; ++ij)
            Z[ij] = (HresB[ij] + Lg[ij] * rms) * TAU_INV;

        float pre[4], post[4];
#pragma unroll
        for (int i = 0; i < 4; ++i) {
            pre[i]  = HpreB[i]  + Lg[16 + i] * rms;
            post[i] = HpostB[i] + Lg[20 + i] * rms;
        }

        float zmax = Z[0];
#pragma unroll
        for (int ij = 1; ij < 16; ++ij) zmax = fmaxf(zmax, Z[ij]);
        float K[16];
#pragma unroll
        for (int ij = 0; ij < 16; ++ij) K[ij] = __expf(Z[ij] - zmax);

        float rr[4], cc[4] = {1.f, 1.f, 1.f, 1.f};
#pragma unroll 1
        for (int it = 0; it < 50; ++it) {
#pragma unroll
            for (int i = 0; i < 4; ++i) {
                float s = fmaf(K[i * 4 + 0], cc[0],
                          fmaf(K[i * 4 + 1], cc[1],
                          fmaf(K[i * 4 + 2], cc[2], K[i * 4 + 3] * cc[3])));
                rr[i] = frcp(s);
            }
#pragma unroll
            for (int j = 0; j < 4; ++j) {
                float s = fmaf(K[0 * 4 + j], rr[0],
                          fmaf(K[1 * 4 + j], rr[1],
                          fmaf(K[2 * 4 + j], rr[2], K[3 * 4 + j] * rr[3])));
                cc[j] = frcp(s);
            }
        }

        {
            float m = fmaxf(fmaxf(pre[0], pre[1]), fmaxf(pre[2], pre[3]));
            float e0 = __expf(pre[0] - m), e1 = __expf(pre[1] - m);
            float e2 = __expf(pre[2] - m), e3 = __expf(pre[3] - m);
            float inv = 1.0f / (e0 + e1 + e2 + e3);
            pre[0] = e0 * inv; pre[1] = e1 * inv; pre[2] = e2 * inv; pre[3] = e3 * inv;
        }
        {
            float m = fmaxf(fmaxf(post[0], post[1]), fmaxf(post[2], post[3]));
            float e0 = __expf(post[0] - m), e1 = __expf(post[1] - m);
            float e2 = __expf(post[2] - m), e3 = __expf(post[3] - m);
            float inv = 1.0f / (e0 + e1 + e2 + e3);
            post[0] = e0 * inv; post[1] = e1 * inv; post[2] = e2 * inv; post[3] = e3 * inv;
        }

        float gv = 1.0f / (1.0f + __expf(-gate[0]));
        float M[16];
#pragma unroll
        for (int i = 0; i < 4; ++i) {
#pragma unroll
            for (int jj = 0; jj < 4; ++jj) {
                float hres = K[i * 4 + jj] * rr[i] * cc[jj];
                float mg   = gv * hres + ((i == jj) ? (1.0f - gv) : 0.0f);
                M[i * 4 + jj] = mg + post[i] * pre[jj];
            }
        }

        float4* mp = reinterpret_cast<float4*>(g_M + (size_t)(t0 + tid) * 16);
        mp[0] = make_float4(M[0],  M[1],  M[2],  M[3]);
        mp[1] = make_float4(M[4],  M[5],  M[6],  M[7]);
        mp[2] = make_float4(M[8],  M[9],  M[10], M[11]);
        mp[3] = make_float4(M[12], M[13], M[14], M[15]);
    }
}

// ---------------------------------------------------------------------------
// Kernel B: out_row = M @ x_streams (reverse token order; ~80% DRAM roofline,
// at its compulsory-traffic floor).
// ---------------------------------------------------------------------------
__global__ __launch_bounds__(256) void mix_kernel(
    const float* __restrict__ x,
    float* __restrict__ out)
{
    const int t = gridDim.x - 1 - blockIdx.x;     // reverse token order
    const float4* Mr = reinterpret_cast<const float4*>(g_M + (size_t)t * 16);
    const float4 m0 = Mr[0];
    const float4 m1 = Mr[1];
    const float4 m2 = Mr[2];
    const float4 m3 = Mr[3];

    const float4* xr = reinterpret_cast<const float4*>(x + (size_t)t * D);
    float4* orow     = reinterpret_cast<float4*>(out + (size_t)t * D);

    const int c = threadIdx.x;
    float4 a0 = __ldcs(&xr[0 * 256 + c]);
    float4 a1 = __ldcs(&xr[1 * 256 + c]);
    float4 a2 = __ldcs(&xr[2 * 256 + c]);
    float4 a3 = __ldcs(&xr[3 * 256 + c]);

    float4 o;
    o.x = fmaf(m0.x, a0.x, fmaf(m0.y, a1.x, fmaf(m0.z, a2.x, m0.w * a3.x)));
    o.y = fmaf(m0.x, a0.y, fmaf(m0.y, a1.y, fmaf(m0.z, a2.y, m0.w * a3.y)));
    o.z = fmaf(m0.x, a0.z, fmaf(m0.y, a1.z, fmaf(m0.z, a2.z, m0.w * a3.z)));
    o.w = fmaf(m0.x, a0.w, fmaf(m0.y, a1.w, fmaf(m0.z, a2.w, m0.w * a3.w)));
    __stcs(&orow[0 * 256 + c], o);
    o.x = fmaf(m1.x, a0.x, fmaf(m1.y, a1.x, fmaf(m1.z, a2.x, m1.w * a3.x)));
    o.y = fmaf(m1.x, a0.y, fmaf(m1.y, a1.y, fmaf(m1.z, a2.y, m1.w * a3.y)));
    o.z = fmaf(m1.x, a0.z, fmaf(m1.y, a1.z, fmaf(m1.z, a2.z, m1.w * a3.z)));
    o.w = fmaf(m1.x, a0.w, fmaf(m1.y, a1.w, fmaf(m1.z, a2.w, m1.w * a3.w)));
    __stcs(&orow[1 * 256 + c], o);
    o.x = fmaf(m2.x, a0.x, fmaf(m2.y, a1.x, fmaf(m2.z, a2.x, m2.w * a3.x)));
    o.y = fmaf(m2.x, a0.y, fmaf(m2.y, a1.y, fmaf(m2.z, a2.y, m2.w * a3.y)));
    o.z = fmaf(m2.x, a0.z, fmaf(m2.y, a1.z, fmaf(m2.z, a2.z, m2.w * a3.z)));
    o.w = fmaf(m2.x, a0.w, fmaf(m2.y, a1.w, fmaf(m2.z, a2.w, m2.w * a3.w)));
    __stcs(&orow[2 * 256 + c], o);
    o.x = fmaf(m3.x, a0.x, fmaf(m3.y, a1.x, fmaf(m3.z, a2.x, m3.w * a3.x)));
    o.y = fmaf(m3.x, a0.y, fmaf(m3.y, a1.y, fmaf(m3.z, a2.y, m3.w * a3.y)));
    o.z = fmaf(m3.x, a0.z, fmaf(m3.y, a1.z, fmaf(m3.z, a2.z, m3.w * a3.z)));
    o.w = fmaf(m3.x, a0.w, fmaf(m3.y, a1.w, fmaf(m3.z, a2.w, m3.w * a3.w)));
    __stcs(&orow[3 * 256 + c], o);
}

// ---------------------------------------------------------------------------
extern "C" void kernel_launch(void* const* d_in, const int* in_sizes, int n_in,
                              void* d_out, int out_size)
{
    const float* x     = (const float*)d_in[0];
    const float* Wres  = (const float*)d_in[1];
    const float* Wpre  = (const float*)d_in[2];
    const float* Wpost = (const float*)d_in[3];
    const float* HresB = (const float*)d_in[4];
    const float* HpreB = (const float*)d_in[5];
    const float* HpostB= (const float*)d_in[6];
    const float* gate  = (const float*)d_in[7];
    float* out         = (float*)d_out;

    const int NT = in_sizes[0] / D;   // 16384 tokens

    static bool attr_set = false;
    if (!attr_set) {
        cudaFuncSetAttribute(logits_kernel,
                             cudaFuncAttributeMaxDynamicSharedMemorySize,
                             4 * STG_F4 * 16);
        attr_set = true;
    }

    packW_kernel<<<96, 256>>>(Wres, Wpre, Wpost);
    logits_kernel<<<NT / 16, 128, 4 * STG_F4 * 16>>>(x, HresB, HpreB, HpostB, gate);
    mix_kernel<<<NT, 256>>>(x, out);
}

// round 17
// speedup vs baseline: 1.6175x; 1.6175x over previous
#include <cuda_runtime.h>
#include <math.h>

#define D 4096
#define NK 24                 // 16 res + 4 pre + 4 post
#define TAU_INV 10.0f
#define RMS_EPS 1.1920929e-07f
#define NTOK 16384
#define CHUNKF 128            // fp32 elements of K per pipeline chunk
#define NCHUNK (D / CHUNKF)   // 32
#define STG_F4 1024           // float4 per stage: x 256 (8 tok) + W 768 (24 rows)

// Scratch (no cudaMalloc allowed)
__device__ float g_logits[(NK + 1) * NTOK];   // [k][token]
__device__ float g_M[NTOK * 16];              // [token][16]
__device__ float g_W[NK * D];                 // packed W: 24 contiguous rows

typedef unsigned long long u64;

__device__ __forceinline__ u64 fma2(u64 a, u64 b, u64 c) {
    u64 d;
    asm("fma.rn.f32x2 %0, %1, %2, %3;" : "=l"(d) : "l"(a), "l"(b), "l"(c));
    return d;
}
__device__ __forceinline__ float pairsum(u64 v) {
    unsigned int lo, hi;
    asm("mov.b64 {%0, %1}, %2;" : "=r"(lo), "=r"(hi) : "l"(v));
    return __uint_as_float(lo) + __uint_as_float(hi);
}
__device__ __forceinline__ float warpSum(float v) {
    v += __shfl_xor_sync(0xffffffffu, v, 16);
    v += __shfl_xor_sync(0xffffffffu, v, 8);
    v += __shfl_xor_sync(0xffffffffu, v, 4);
    v += __shfl_xor_sync(0xffffffffu, v, 2);
    v += __shfl_xor_sync(0xffffffffu, v, 1);
    return v;
}
__device__ __forceinline__ float frcp(float x) {
    float y;
    asm("rcp.approx.f32 %0, %1;" : "=f"(y) : "f"(x));
    return y;
}

// ---------------------------------------------------------------------------
// pack W into one contiguous [24][4096] buffer
// ---------------------------------------------------------------------------
__global__ __launch_bounds__(256) void packW_kernel(
    const float* __restrict__ Wres,
    const float* __restrict__ Wpre,
    const float* __restrict__ Wpost)
{
    int i = blockIdx.x * 256 + threadIdx.x;       // float4 index, 24576 total
    int k = i >> 10;                              // row (1024 float4 per row)
    float4 v;
    if (k < 16)      v = reinterpret_cast<const float4*>(Wres)[i];
    else if (k < 20) v = reinterpret_cast<const float4*>(Wpre)[i - 16 * 1024];
    else             v = reinterpret_cast<const float4*>(Wpost)[i - 20 * 1024];
    reinterpret_cast<float4*>(g_W)[i] = v;
}

// ---------------------------------------------------------------------------
// Kernel A: 24 dots + sumsq per token.
// NEW SHAPE: 2048 CTAs x 128 threads (4 warps), 8 tokens/CTA, 3 CTAs/SM
// (launch_bounds(128,3) caps regs at 170; acc tile = 6 rows x 8 tokens =
// 48 f32x2 = 96 regs -> ~145 total, fits without spill).
// 12 warps/SM (vs 8) for better latency hiding — logits was bubble-bound.
// Stage = 128 d-floats: x 4KB (8 tok) + W 12KB = 16KB; 4 stages = 64KB/CTA,
// 3 CTAs x 64KB = 192KB <= 227KB. Single barrier per chunk (4-stage rule).
// ---------------------------------------------------------------------------
__global__ __launch_bounds__(128, 3) void logits_kernel(
    const float* __restrict__ x, int NT)
{
    extern __shared__ float4 smem[];              // 4 x 1024 float4 = 64KB

    const int tid  = threadIdx.x;
    const int lane = tid & 31;
    const int r    = tid >> 5;                    // warp = row group (6 rows)
    const int t0   = blockIdx.x * 8;

    unsigned int smem_base;
    asm("{ .reg .u64 t; cvta.to.shared.u64 t, %1; cvt.u32.u64 %0, t; }"
        : "=r"(smem_base) : "l"(smem));

    const float4* __restrict__ xsrc = reinterpret_cast<const float4*>(x);
    const float4* __restrict__ wsrc = reinterpret_cast<const float4*>(g_W);
    const ulonglong2* __restrict__ S = reinterpret_cast<const ulonglong2*>(smem);

    u64 acc[6][8];
#pragma unroll
    for (int i = 0; i < 6; ++i)
#pragma unroll
        for (int t = 0; t < 8; ++t) acc[i][t] = 0ULL;
    u64 ss0 = 0ULL, ss1 = 0ULL;                   // sumsq: tokens 2r, 2r+1

    // ---- stage issuer: 8 cp.asyncs/thread (x: 256 f4, W: 768 f4) ----
    auto issue_stage = [&](int stg, int c) {
#pragma unroll
        for (int n = 0; n < 8; ++n) {
            int i = n * 128 + tid;                // 0..1023
            const float4* src;
            if (n < 2) {                          // i < 256 : x (8 tokens x 32 f4)
                int t = i >> 5;
                int f = i & 31;
                src = xsrc + (size_t)(t0 + t) * 1024 + c * 32 + f;
            } else {                              // W (24 rows x 32 f4)
                int k = (i - 256) >> 5;
                int f = i & 31;
                src = wsrc + k * 1024 + c * 32 + f;
            }
            unsigned int dst = smem_base + (unsigned)(stg * STG_F4 + i) * 16u;
            asm volatile("cp.async.cg.shared.global [%0], [%1], 16;"
                         :: "r"(dst), "l"(src) : "memory");
        }
        asm volatile("cp.async.commit_group;" ::: "memory");
    };

    issue_stage(0, 0);
    issue_stage(1, 1);
    issue_stage(2, 2);

#pragma unroll 1
    for (int c = 0; c < NCHUNK; ++c) {
        if (c <= NCHUNK - 3)      asm volatile("cp.async.wait_group 2;" ::: "memory");
        else if (c == NCHUNK - 2) asm volatile("cp.async.wait_group 1;" ::: "memory");
        else                      asm volatile("cp.async.wait_group 0;" ::: "memory");
        __syncthreads();                          // single barrier per chunk

        if (c + 3 < NCHUNK) issue_stage((c + 3) & 3, c + 3);

        const int sb = (c & 3) * STG_F4;          // 16B units

        // 6 W rows for this warp, held in registers across the token loop
        ulonglong2 w0 = S[sb + 256 + (6 * r + 0) * 32 + lane];
        ulonglong2 w1 = S[sb + 256 + (6 * r + 1) * 32 + lane];
        ulonglong2 w2 = S[sb + 256 + (6 * r + 2) * 32 + lane];
        ulonglong2 w3 = S[sb + 256 + (6 * r + 3) * 32 + lane];
        ulonglong2 w4 = S[sb + 256 + (6 * r + 4) * 32 + lane];
        ulonglong2 w5 = S[sb + 256 + (6 * r + 5) * 32 + lane];

#pragma unroll
        for (int t = 0; t < 8; ++t) {
            ulonglong2 a = S[sb + t * 32 + lane];
            acc[0][t] = fma2(a.x, w0.x, acc[0][t]);
            acc[0][t] = fma2(a.y, w0.y, acc[0][t]);
            acc[1][t] = fma2(a.x, w1.x, acc[1][t]);
            acc[1][t] = fma2(a.y, w1.y, acc[1][t]);
            acc[2][t] = fma2(a.x, w2.x, acc[2][t]);
            acc[2][t] = fma2(a.y, w2.y, acc[2][t]);
            acc[3][t] = fma2(a.x, w3.x, acc[3][t]);
            acc[3][t] = fma2(a.y, w3.y, acc[3][t]);
            acc[4][t] = fma2(a.x, w4.x, acc[4][t]);
            acc[4][t] = fma2(a.y, w4.y, acc[4][t]);
            acc[5][t] = fma2(a.x, w5.x, acc[5][t]);
            acc[5][t] = fma2(a.y, w5.y, acc[5][t]);
            if (t == 2 * r)     { ss0 = fma2(a.x, a.x, ss0); ss0 = fma2(a.y, a.y, ss0); }
            if (t == 2 * r + 1) { ss1 = fma2(a.x, a.x, ss1); ss1 = fma2(a.y, a.y, ss1); }
        }
    }

    // ---- reduce & store ----
#pragma unroll
    for (int i = 0; i < 6; ++i) {
#pragma unroll
        for (int t = 0; t < 8; ++t) {
            float v = warpSum(pairsum(acc[i][t]));
            if (lane == 0)
                g_logits[(size_t)(6 * r + i) * NT + t0 + t] = v;
        }
    }
    {
        float v0 = warpSum(pairsum(ss0));
        float v1 = warpSum(pairsum(ss1));
        if (lane == 0) {
            g_logits[(size_t)NK * NT + t0 + 2 * r]     = v0;
            g_logits[(size_t)NK * NT + t0 + 2 * r + 1] = v1;
        }
    }
}

// ---------------------------------------------------------------------------
// Kernel A2: RMS scale, Sinkhorn(50) in PROBABILITY domain, softmaxes -> M.
// ---------------------------------------------------------------------------
__global__ __launch_bounds__(128) void sinkhorn_kernel(
    const float* __restrict__ HresB,
    const float* __restrict__ HpreB,
    const float* __restrict__ HpostB,
    const float* __restrict__ gate,
    int NT)
{
    int t = blockIdx.x * 128 + threadIdx.x;
    if (t >= NT) return;

    float ssv = g_logits[(size_t)NK * NT + t];
    float rms = rsqrtf(ssv * (1.0f / (float)D) + RMS_EPS);

    float Z[16];
#pragma unroll
    for (int ij = 0; ij < 16; ++ij)
        Z[ij] = (HresB[ij] + g_logits[(size_t)ij * NT + t] * rms) * TAU_INV;

    float pre[4], post[4];
#pragma unroll
    for (int i = 0; i < 4; ++i) {
        pre[i]  = HpreB[i]  + g_logits[(size_t)(16 + i) * NT + t] * rms;
        post[i] = HpostB[i] + g_logits[(size_t)(20 + i) * NT + t] * rms;
    }

    // K = exp(Z - Zmax)  (shift-invariant; keeps K <= 1)
    float zmax = Z[0];
#pragma unroll
    for (int ij = 1; ij < 16; ++ij) zmax = fmaxf(zmax, Z[ij]);
    float K[16];
#pragma unroll
    for (int ij = 0; ij < 16; ++ij) K[ij] = __expf(Z[ij] - zmax);

    // scaling-domain Sinkhorn: r = 1/(K c); c = 1/(K^T r)
    float rr[4], cc[4] = {1.f, 1.f, 1.f, 1.f};
#pragma unroll 1
    for (int it = 0; it < 50; ++it) {
#pragma unroll
        for (int i = 0; i < 4; ++i) {
            float s = fmaf(K[i * 4 + 0], cc[0],
                      fmaf(K[i * 4 + 1], cc[1],
                      fmaf(K[i * 4 + 2], cc[2], K[i * 4 + 3] * cc[3])));
            rr[i] = frcp(s);
        }
#pragma unroll
        for (int j = 0; j < 4; ++j) {
            float s = fmaf(K[0 * 4 + j], rr[0],
                      fmaf(K[1 * 4 + j], rr[1],
                      fmaf(K[2 * 4 + j], rr[2], K[3 * 4 + j] * rr[3])));
            cc[j] = frcp(s);
        }
    }

    // softmax(pre), softmax(post)
    {
        float m = fmaxf(fmaxf(pre[0], pre[1]), fmaxf(pre[2], pre[3]));
        float e0 = __expf(pre[0] - m), e1 = __expf(pre[1] - m);
        float e2 = __expf(pre[2] - m), e3 = __expf(pre[3] - m);
        float inv = 1.0f / (e0 + e1 + e2 + e3);
        pre[0] = e0 * inv; pre[1] = e1 * inv; pre[2] = e2 * inv; pre[3] = e3 * inv;
    }
    {
        float m = fmaxf(fmaxf(post[0], post[1]), fmaxf(post[2], post[3]));
        float e0 = __expf(post[0] - m), e1 = __expf(post[1] - m);
        float e2 = __expf(post[2] - m), e3 = __expf(post[3] - m);
        float inv = 1.0f / (e0 + e1 + e2 + e3);
        post[0] = e0 * inv; post[1] = e1 * inv; post[2] = e2 * inv; post[3] = e3 * inv;
    }

    float gv = 1.0f / (1.0f + __expf(-gate[0]));
    float M[16];
#pragma unroll
    for (int i = 0; i < 4; ++i) {
#pragma unroll
        for (int jj = 0; jj < 4; ++jj) {
            float hres = K[i * 4 + jj] * rr[i] * cc[jj];
            float mg   = gv * hres + ((i == jj) ? (1.0f - gv) : 0.0f);
            M[i * 4 + jj] = mg + post[i] * pre[jj];
        }
    }

    float4* mp = reinterpret_cast<float4*>(g_M + (size_t)t * 16);
    mp[0] = make_float4(M[0],  M[1],  M[2],  M[3]);
    mp[1] = make_float4(M[4],  M[5],  M[6],  M[7]);
    mp[2] = make_float4(M[8],  M[9],  M[10], M[11]);
    mp[3] = make_float4(M[12], M[13], M[14], M[15]);
}

// ---------------------------------------------------------------------------
// Kernel B: out_row = M @ x_streams (reverse token order; ~80% DRAM roofline,
// at its compulsory-traffic floor).
// ---------------------------------------------------------------------------
__global__ __launch_bounds__(256) void mix_kernel(
    const float* __restrict__ x,
    float* __restrict__ out)
{
    const int t = gridDim.x - 1 - blockIdx.x;     // reverse token order
    const float4* Mr = reinterpret_cast<const float4*>(g_M + (size_t)t * 16);
    const float4 m0 = Mr[0];
    const float4 m1 = Mr[1];
    const float4 m2 = Mr[2];
    const float4 m3 = Mr[3];

    const float4* xr = reinterpret_cast<const float4*>(x + (size_t)t * D);
    float4* orow     = reinterpret_cast<float4*>(out + (size_t)t * D);

    const int c = threadIdx.x;
    float4 a0 = __ldcs(&xr[0 * 256 + c]);
    float4 a1 = __ldcs(&xr[1 * 256 + c]);
    float4 a2 = __ldcs(&xr[2 * 256 + c]);
    float4 a3 = __ldcs(&xr[3 * 256 + c]);

    float4 o;
    o.x = fmaf(m0.x, a0.x, fmaf(m0.y, a1.x, fmaf(m0.z, a2.x, m0.w * a3.x)));
    o.y = fmaf(m0.x, a0.y, fmaf(m0.y, a1.y, fmaf(m0.z, a2.y, m0.w * a3.y)));
    o.z = fmaf(m0.x, a0.z, fmaf(m0.y, a1.z, fmaf(m0.z, a2.z, m0.w * a3.z)));
    o.w = fmaf(m0.x, a0.w, fmaf(m0.y, a1.w, fmaf(m0.z, a2.w, m0.w * a3.w)));
    __stcs(&orow[0 * 256 + c], o);
    o.x = fmaf(m1.x, a0.x, fmaf(m1.y, a1.x, fmaf(m1.z, a2.x, m1.w * a3.x)));
    o.y = fmaf(m1.x, a0.y, fmaf(m1.y, a1.y, fmaf(m1.z, a2.y, m1.w * a3.y)));
    o.z = fmaf(m1.x, a0.z, fmaf(m1.y, a1.z, fmaf(m1.z, a2.z, m1.w * a3.z)));
    o.w = fmaf(m1.x, a0.w, fmaf(m1.y, a1.w, fmaf(m1.z, a2.w, m1.w * a3.w)));
    __stcs(&orow[1 * 256 + c], o);
    o.x = fmaf(m2.x, a0.x, fmaf(m2.y, a1.x, fmaf(m2.z, a2.x, m2.w * a3.x)));
    o.y = fmaf(m2.x, a0.y, fmaf(m2.y, a1.y, fmaf(m2.z, a2.y, m2.w * a3.y)));
    o.z = fmaf(m2.x, a0.z, fmaf(m2.y, a1.z, fmaf(m2.z, a2.z, m2.w * a3.z)));
    o.w = fmaf(m2.x, a0.w, fmaf(m2.y, a1.w, fmaf(m2.z, a2.w, m2.w * a3.w)));
    __stcs(&orow[2 * 256 + c], o);
    o.x = fmaf(m3.x, a0.x, fmaf(m3.y, a1.x, fmaf(m3.z, a2.x, m3.w * a3.x)));
    o.y = fmaf(m3.x, a0.y, fmaf(m3.y, a1.y, fmaf(m3.z, a2.y, m3.w * a3.y)));
    o.z = fmaf(m3.x, a0.z, fmaf(m3.y, a1.z, fmaf(m3.z, a2.z, m3.w * a3.z)));
    o.w = fmaf(m3.x, a0.w, fmaf(m3.y, a1.w, fmaf(m3.z, a2.w, m3.w * a3.w)));
    __stcs(&orow[3 * 256 + c], o);
}

// ---------------------------------------------------------------------------
extern "C" void kernel_launch(void* const* d_in, const int* in_sizes, int n_in,
                              void* d_out, int out_size)
{
    const float* x     = (const float*)d_in[0];
    const float* Wres  = (const float*)d_in[1];
    const float* Wpre  = (const float*)d_in[2];
    const float* Wpost = (const float*)d_in[3];
    const float* HresB = (const float*)d_in[4];
    const float* HpreB = (const float*)d_in[5];
    const float* HpostB= (const float*)d_in[6];
    const float* gate  = (const float*)d_in[7];
    float* out         = (float*)d_out;

    const int NT = in_sizes[0] / D;   // 16384 tokens

    static bool attr_set = false;
    if (!attr_set) {
        cudaFuncSetAttribute(logits_kernel,
                             cudaFuncAttributeMaxDynamicSharedMemorySize,
                             4 * STG_F4 * 16);
        attr_set = true;
    }

    packW_kernel<<<96, 256>>>(Wres, Wpre, Wpost);
    logits_kernel<<<NT / 8, 128, 4 * STG_F4 * 16>>>(x, NT);
    sinkhorn_kernel<<<(NT + 127) / 128, 128>>>(HresB, HpreB, HpostB, gate, NT);
    mix_kernel<<<NT, 256>>>(x, out);
}